// round 17
// baseline (speedup 1.0000x reference)
#include <cuda_runtime.h>
#include <cuda_fp16.h>
#include <cstdint>
#include <cstring>

#define NN 8192
#define DIM 128
#define KCHUNK 64
#define NITER (NN / KCHUNK)            // 128
#define HITER (NITER / 2)              // 64 chunks per half
#define MTILE 64
#define TPB 256
#define TILE_STRIDE_H 136              // B: halves per k-row (128 + 8 pad) -> 272 B
#define TILE_BYTES (KCHUNK * TILE_STRIDE_H * 2)   // 17408
#define DSTRIDE_B 272                  // dist tile row stride bytes (68 floats)
#define HALF_BYTES (4 * TILE_BYTES)    // B ring (2) + D ring (2)
#define W2_OFF (8 * TILE_BYTES)        // 139264
#define SMEM_TOTAL (W2_OFF + NN * 8)   // 204800
#define WSCALE 0.015625f

__device__ float2 g_W2[NN];            // (exp(s2), exp(0.2 s2))
__device__ float2 g_E1F1[NN];          // WSCALE * (exp(s1), exp(0.2 s1))
__device__ __align__(16) __half g_Bt[NITER * KCHUNK * TILE_STRIDE_H];

// ---------------- helpers ----------------
__device__ __forceinline__ uint32_t smem_u32(const void* p) {
    uint32_t r;
    asm("{ .reg .u64 t; cvta.to.shared.u64 t, %1; cvt.u32.u64 %0, t; }" : "=r"(r) : "l"(p));
    return r;
}
__device__ __forceinline__ void cp16(uint32_t d, const void* s) {
    asm volatile("cp.async.cg.shared.global [%0], [%1], 16;" :: "r"(d), "l"(s) : "memory");
}
#define CP_COMMIT() asm volatile("cp.async.commit_group;" ::: "memory")
#define CP_WAIT1() asm volatile("cp.async.wait_group 1;" ::: "memory")
#define CP_WAIT0() asm volatile("cp.async.wait_group 0;" ::: "memory")

__device__ __forceinline__ void ldm4t(uint32_t& r0, uint32_t& r1, uint32_t& r2, uint32_t& r3, uint32_t a) {
    asm volatile("ldmatrix.sync.aligned.m8n8.x4.trans.shared.b16 {%0,%1,%2,%3}, [%4];"
        : "=r"(r0), "=r"(r1), "=r"(r2), "=r"(r3) : "r"(a));
}
// fp16-accumulate MMA
__device__ __forceinline__ void mma16816h(uint32_t* d, const uint32_t* a, uint32_t b0, uint32_t b1) {
    asm volatile("mma.sync.aligned.m16n8k16.row.col.f16.f16.f16.f16 "
        "{%0,%1},{%2,%3,%4,%5},{%6,%7},{%0,%1};"
        : "+r"(d[0]), "+r"(d[1])
        : "r"(a[0]), "r"(a[1]), "r"(a[2]), "r"(a[3]), "r"(b0), "r"(b1));
}
__device__ __forceinline__ uint32_t pack_h2(float a, float b) {
    __half2 h = __floats2half2_rn(a, b);
    uint32_t u;
    memcpy(&u, &h, 4);
    return u;
}

// ---------------- prep 1: per-node exponentials ----------------
__global__ void prep_stats(const float* __restrict__ nodes, const float* __restrict__ a) {
    int gw = blockIdx.x * 8 + (threadIdx.x >> 5);
    int lane = threadIdx.x & 31;
    float4 x = *(const float4*)(nodes + (size_t)gw * DIM + lane * 4);
    float4 w1 = *(const float4*)(a + lane * 4);
    float4 w2 = *(const float4*)(a + DIM + lane * 4);
    float v1 = x.x * w1.x + x.y * w1.y + x.z * w1.z + x.w * w1.w;
    float v2 = x.x * w2.x + x.y * w2.y + x.z * w2.z + x.w * w2.w;
    #pragma unroll
    for (int o = 16; o; o >>= 1) {
        v1 += __shfl_xor_sync(0xFFFFFFFFu, v1, o);
        v2 += __shfl_xor_sync(0xFFFFFFFFu, v2, o);
    }
    if (lane == 0) {
        g_E1F1[gw] = make_float2(WSCALE * expf(v1), WSCALE * expf(0.2f * v1));
        g_W2[gw] = make_float2(expf(v2), expf(0.2f * v2));
    }
}

// ---------------- prep 2: fp16 B tiles, padded k-major layout ----------------
__global__ void prep_b(const float* __restrict__ nodes) {
    int id = blockIdx.x * 256 + threadIdx.x;   // NN*16 threads
    int ng = id & 15;
    int k = id >> 4;
    const float4* src = (const float4*)(nodes + (size_t)k * DIM + ng * 8);
    float4 x = src[0], y = src[1];
    uint4 u;
    u.x = pack_h2(x.x, x.y); u.y = pack_h2(x.z, x.w);
    u.z = pack_h2(y.x, y.y); u.w = pack_h2(y.z, y.w);
    int t = k >> 6, kk = k & 63;
    __half* dst = g_Bt + (size_t)t * (KCHUNK * TILE_STRIDE_H) + kk * TILE_STRIDE_H + ng * 8;
    *(uint4*)dst = u;
}

// ---------------- main kernel: 8 warps, K-split halves, smem-staged dist ----------------
__global__ void __launch_bounds__(TPB, 1)
gat_main(const float* __restrict__ dist, float* __restrict__ out) {
    extern __shared__ char smem[];
    uint32_t sb = smem_u32(smem);
    int tid = threadIdx.x;
    int lane = tid & 31;
    int half = tid >> 7;               // 0: chunks 0..63, 1: chunks 64..127
    int q = tid & 127;                 // index within half
    int wi = (tid >> 5) & 3;           // warp-in-half
    int g = lane >> 2, c = lane & 3;
    int rloc0 = wi * 16 + g;           // local row; +8 for second row
    int rowBase = blockIdx.x * MTILE;
    int row0 = rowBase + rloc0;
    int t0 = half * HITER;
    uint32_t hb = sb + half * HALF_BYTES;          // this half's rings
    uint32_t dringb = hb + 2 * TILE_BYTES;         // dist ring base
    int barid = 1 + half;

    // per-thread dist cp assignment: row q>>1, 8 contiguous 16B segs
    int drow = q >> 1;
    int dsg = (q & 1) * 8;
    const char* distRow = (const char*)(dist + (size_t)(rowBase + drow) * NN) + dsg * 16;
    uint32_t ddstBase = drow * DSTRIDE_B + dsg * 16;

    // ---- prologue: G0 = {W2, B[0], D[0]}, G1 = {B[1], D[1]} ----
    #pragma unroll
    for (int i = 0; i < 16; i++)
        cp16(sb + W2_OFF + (tid + i * TPB) * 16, (const char*)g_W2 + (tid + i * TPB) * 16);
    {
        const char* srcs = (const char*)g_Bt + (size_t)t0 * TILE_BYTES;
        #pragma unroll
        for (int i = 0; i < 9; i++) {
            int off = q * 16 + i * (128 * 16);
            if (off < TILE_BYTES) cp16(hb + off, srcs + off);
        }
        const char* dsrc = distRow + (size_t)(t0 * KCHUNK) * 4;
        #pragma unroll
        for (int i = 0; i < 8; i++)
            cp16(dringb + ddstBase + i * 16, dsrc + i * 16);
    }
    CP_COMMIT();
    {
        const char* srcs = (const char*)g_Bt + (size_t)(t0 + 1) * TILE_BYTES;
        #pragma unroll
        for (int i = 0; i < 9; i++) {
            int off = q * 16 + i * (128 * 16);
            if (off < TILE_BYTES) cp16(hb + TILE_BYTES + off, srcs + off);
        }
        const char* dsrc = distRow + (size_t)((t0 + 1) * KCHUNK) * 4;
        #pragma unroll
        for (int i = 0; i < 8; i++)
            cp16(dringb + TILE_BYTES + ddstBase + i * 16, dsrc + i * 16);
    }
    CP_COMMIT();

    float2 ef0 = g_E1F1[row0];
    float2 ef1 = g_E1F1[row0 + 8];

    float acc[16][4];
    #pragma unroll
    for (int p = 0; p < 16; p++)
        #pragma unroll
        for (int v = 0; v < 4; v++) acc[p][v] = 0.0f;
    float dn0 = 0.0f, dn1 = 0.0f;

    int m = lane >> 3, r = lane & 7;
    uint32_t lbase = ((m & 1) * 8 + r) * (TILE_STRIDE_H * 2) + ((m >> 1) * 8) * 2;

    for (int tt = 0; tt < HITER; tt++) {
        int t = t0 + tt;
        CP_WAIT1();
        asm volatile("bar.sync %0, 128;" :: "r"(barid) : "memory");

        const char* dtile = smem + (half * HALF_BYTES + 2 * TILE_BYTES) + (tt & 1) * TILE_BYTES;
        const char* d0 = dtile + rloc0 * DSTRIDE_B;
        const char* d1 = dtile + (rloc0 + 8) * DSTRIDE_B;

        // ---- build A fragments for chunk t (dist from smem) ----
        uint32_t ah[4][4];
        #pragma unroll
        for (int ks = 0; ks < 4; ks++) {
            int kk = ks * 16 + 2 * c;
            int kg = t * KCHUNK + kk;
            float4 Wa = *(const float4*)(smem + W2_OFF + kg * 8);
            float4 Wb = *(const float4*)(smem + W2_OFF + (kg + 8) * 8);
            float2 da = *(const float2*)(d0 + kk * 4);
            float2 db = *(const float2*)(d0 + kk * 4 + 32);
            float2 dc = *(const float2*)(d1 + kk * 4);
            float2 dd = *(const float2*)(d1 + kk * 4 + 32);
            float w00 = (da.x < 0.5f) ? fmaxf(ef0.x * Wa.x, ef0.y * Wa.y) : 0.0f;
            float w01 = (da.y < 0.5f) ? fmaxf(ef0.x * Wa.z, ef0.y * Wa.w) : 0.0f;
            float w02 = (db.x < 0.5f) ? fmaxf(ef0.x * Wb.x, ef0.y * Wb.y) : 0.0f;
            float w03 = (db.y < 0.5f) ? fmaxf(ef0.x * Wb.z, ef0.y * Wb.w) : 0.0f;
            float w10 = (dc.x < 0.5f) ? fmaxf(ef1.x * Wa.x, ef1.y * Wa.y) : 0.0f;
            float w11 = (dc.y < 0.5f) ? fmaxf(ef1.x * Wa.z, ef1.y * Wa.w) : 0.0f;
            float w12 = (dd.x < 0.5f) ? fmaxf(ef1.x * Wb.x, ef1.y * Wb.y) : 0.0f;
            float w13 = (dd.y < 0.5f) ? fmaxf(ef1.x * Wb.z, ef1.y * Wb.w) : 0.0f;
            dn0 += (w00 + w01) + (w02 + w03);
            dn1 += (w10 + w11) + (w12 + w13);
            ah[ks][0] = pack_h2(w00, w01);
            ah[ks][1] = pack_h2(w10, w11);
            ah[ks][2] = pack_h2(w02, w03);
            ah[ks][3] = pack_h2(w12, w13);
        }

        // ---- MMA (fp16 accumulate within chunk) ----
        uint32_t hacc[16][2];
        #pragma unroll
        for (int p = 0; p < 16; p++) { hacc[p][0] = 0u; hacc[p][1] = 0u; }

        uint32_t bs = hb + (tt & 1) * TILE_BYTES + lbase;
        #pragma unroll
        for (int ks = 0; ks < 4; ks++) {
            #pragma unroll
            for (int p = 0; p < 8; p++) {
                uint32_t b0, b1, b2, b3;
                ldm4t(b0, b1, b2, b3, bs + ks * (16 * TILE_STRIDE_H * 2) + p * 32);
                mma16816h(hacc[2 * p], ah[ks], b0, b1);
                mma16816h(hacc[2 * p + 1], ah[ks], b2, b3);
            }
        }

        // ---- promote chunk partials to fp32 master accumulators ----
        #pragma unroll
        for (int p = 0; p < 16; p++) {
            __half2 h0, h1;
            memcpy(&h0, &hacc[p][0], 4);
            memcpy(&h1, &hacc[p][1], 4);
            float2 lo = __half22float2(h0);
            float2 hi = __half22float2(h1);
            acc[p][0] += lo.x; acc[p][1] += lo.y;
            acc[p][2] += hi.x; acc[p][3] += hi.y;
        }

        // ---- all consumed; refill the slot just freed with chunk tt+2 ----
        asm volatile("bar.sync %0, 128;" :: "r"(barid) : "memory");
        if (tt + 2 < HITER) {
            const char* srcs = (const char*)g_Bt + (size_t)(t + 2) * TILE_BYTES;
            uint32_t bdst = hb + (tt & 1) * TILE_BYTES;
            #pragma unroll
            for (int i = 0; i < 9; i++) {
                int off = q * 16 + i * (128 * 16);
                if (off < TILE_BYTES) cp16(bdst + off, srcs + off);
            }
            const char* dsrc = distRow + (size_t)((t + 2) * KCHUNK) * 4;
            uint32_t ddst = dringb + (tt & 1) * TILE_BYTES + ddstBase;
            #pragma unroll
            for (int i = 0; i < 8; i++)
                cp16(ddst + i * 16, dsrc + i * 16);
        }
        CP_COMMIT();
    }

    // ---- epilogue: combine halves via smem, normalize, store ----
    CP_WAIT0();
    __syncthreads();
    float* red = (float*)smem;    // reuse ring area: 128 threads * 68 floats
    if (half == 1) {
        float* rr = red + q * 68;
        #pragma unroll
        for (int p = 0; p < 16; p++)
            *(float4*)(rr + p * 4) = make_float4(acc[p][0], acc[p][1], acc[p][2], acc[p][3]);
        rr[64] = dn0;
        rr[65] = dn1;
    }
    __syncthreads();
    if (half == 0) {
        const float* rr = red + q * 68;
        #pragma unroll
        for (int p = 0; p < 16; p++) {
            float4 o = *(const float4*)(rr + p * 4);
            acc[p][0] += o.x; acc[p][1] += o.y; acc[p][2] += o.z; acc[p][3] += o.w;
        }
        dn0 += rr[64];
        dn1 += rr[65];
        dn0 += __shfl_xor_sync(0xFFFFFFFFu, dn0, 1);
        dn0 += __shfl_xor_sync(0xFFFFFFFFu, dn0, 2);
        dn1 += __shfl_xor_sync(0xFFFFFFFFu, dn1, 1);
        dn1 += __shfl_xor_sync(0xFFFFFFFFu, dn1, 2);
        float inv0 = 1.0f / dn0;
        float inv1 = 1.0f / dn1;
        float* o0 = out + (size_t)row0 * DIM + 2 * c;
        float* o1 = out + (size_t)(row0 + 8) * DIM + 2 * c;
        #pragma unroll
        for (int p = 0; p < 16; p++) {
            *(float2*)(o0 + p * 8) = make_float2(acc[p][0] * inv0, acc[p][1] * inv0);
            *(float2*)(o1 + p * 8) = make_float2(acc[p][2] * inv1, acc[p][3] * inv1);
        }
    }
}

extern "C" void kernel_launch(void* const* d_in, const int* in_sizes, int n_in,
                              void* d_out, int out_size) {
    const float* nodes = nullptr;
    const float* dist = nullptr;
    const float* a = nullptr;
    for (int i = 0; i < n_in; i++) {
        if (in_sizes[i] == NN * NN) dist = (const float*)d_in[i];
        else if (in_sizes[i] == NN * DIM) nodes = (const float*)d_in[i];
        else if (in_sizes[i] == 2 * DIM) a = (const float*)d_in[i];
    }
    float* out = (float*)d_out;

    static bool attr_set = false;
    if (!attr_set) {
        cudaFuncSetAttribute(gat_main, cudaFuncAttributeMaxDynamicSharedMemorySize, SMEM_TOTAL);
        attr_set = true;
    }

    prep_stats<<<NN / 8, 256>>>(nodes, a);
    prep_b<<<(NN * 16) / 256, 256>>>(nodes);
    gat_main<<<NN / MTILE, TPB, SMEM_TOTAL>>>(dist, out);
}